// round 1
// baseline (speedup 1.0000x reference)
#include <cuda_runtime.h>
#include <cuda_bf16.h>

// Problem constants
#define BATCH 32
#define NN    1024          // N (nodes / feature dim of sc rows)
#define DD    512           // hidden dim
#define LN_EPS 1e-5f

// GEMM tile config
#define BM 128
#define BN 128
#define BK 16

// ---------------------------------------------------------------------------
// Scratch (device globals; no allocation allowed in kernel_launch)
// ---------------------------------------------------------------------------
__device__ float g_buf0[(size_t)BATCH * NN * DD];    // 64 MB
__device__ float g_buf1[(size_t)BATCH * NN * DD];    // 64 MB
__device__ float g_dis[BATCH * NN];
__device__ float g_partial[BATCH * 8 * DD];          // LN+pool partials

// ---------------------------------------------------------------------------
// 1) dis[b,j] = rsqrt( sum_i A[b,i,j] )   (column sums of A)
// ---------------------------------------------------------------------------
__global__ void deg_kernel(const float* __restrict__ A, float* __restrict__ dis)
{
    int b = blockIdx.y;
    int j = blockIdx.x * 256 + threadIdx.x;
    const float* Ab = A + (size_t)b * NN * NN;
    float s = 0.f;
#pragma unroll 8
    for (int i = 0; i < NN; i++)
        s += Ab[(size_t)i * NN + j];
    dis[b * NN + j] = (s > 0.f) ? rsqrtf(s) : 0.f;
}

// ---------------------------------------------------------------------------
// Tiled SGEMM.
//   TRANSA=0 : A[m*lda + k]     (row-major A)
//   TRANSA=1 : A[k*lda + m]     (computes A_stored^T @ B; coalesced row loads)
//   B is always B[k*ldb + n].
// Epilogue:
//   EPI=0 : C = acc * dis[m]
//   EPI=1 : C = relu(acc * dis[m] + bias[n])
//   EPI=2 : C = acc * dis[m] + bias[n]
// blockIdx.z = batch index; strides advance base pointers per batch.
// All dims are exact multiples of the tile sizes (checked on host side).
// ---------------------------------------------------------------------------
template<int TRANSA, int EPI>
__global__ void __launch_bounds__(256, 2) gemm_k(
    const float* __restrict__ A, const float* __restrict__ Bm, float* __restrict__ C,
    int K, int lda, int ldb, int ldc,
    long sA, long sB, long sC,
    const float* __restrict__ dis, int sDis,
    const float* __restrict__ bias)
{
    int bz = blockIdx.z;
    A   += (long)bz * sA;
    Bm  += (long)bz * sB;
    C   += (long)bz * sC;
    dis += (long)bz * sDis;

    const int m0 = blockIdx.y * BM;
    const int n0 = blockIdx.x * BN;
    const int tid = threadIdx.x;
    const int tx = tid & 15;
    const int ty = tid >> 4;

    __shared__ float As[BK][BM];
    __shared__ float Bs[BK][BN];

    float acc[8][8];
#pragma unroll
    for (int i = 0; i < 8; i++)
#pragma unroll
        for (int j = 0; j < 8; j++) acc[i][j] = 0.f;

    for (int k0 = 0; k0 < K; k0 += BK) {
        // ---- load A tile into As[k][m] ----
        if (TRANSA) {
            // stored A[k*lda + m]: 16 rows x 128 cols, direct vector copy
#pragma unroll
            for (int r = 0; r < 2; r++) {
                int idx = tid + r * 256;          // 0..511 float4s
                int kr  = idx >> 5;               // 0..15
                int mc  = (idx & 31) << 2;        // 0..124
                float4 v = *reinterpret_cast<const float4*>(
                    &A[(long)(k0 + kr) * lda + m0 + mc]);
                *reinterpret_cast<float4*>(&As[kr][mc]) = v;
            }
        } else {
            // stored A[m*lda + k]: 128 rows x 16 cols, transpose into As
#pragma unroll
            for (int r = 0; r < 2; r++) {
                int idx = tid + r * 256;
                int mr  = idx >> 2;               // 0..127
                int kc  = (idx & 3) << 2;         // 0,4,8,12
                float4 v = *reinterpret_cast<const float4*>(
                    &A[(long)(m0 + mr) * lda + k0 + kc]);
                As[kc + 0][mr] = v.x;
                As[kc + 1][mr] = v.y;
                As[kc + 2][mr] = v.z;
                As[kc + 3][mr] = v.w;
            }
        }
        // ---- load B tile: 16 rows x 128 cols ----
#pragma unroll
        for (int r = 0; r < 2; r++) {
            int idx = tid + r * 256;
            int kr  = idx >> 5;
            int nc  = (idx & 31) << 2;
            float4 v = *reinterpret_cast<const float4*>(
                &Bm[(long)(k0 + kr) * ldb + n0 + nc]);
            *reinterpret_cast<float4*>(&Bs[kr][nc]) = v;
        }
        __syncthreads();

#pragma unroll
        for (int kk = 0; kk < BK; kk++) {
            float a[8], b[8];
#pragma unroll
            for (int i = 0; i < 8; i += 4)
                *reinterpret_cast<float4*>(&a[i]) =
                    *reinterpret_cast<const float4*>(&As[kk][ty * 8 + i]);
#pragma unroll
            for (int j = 0; j < 8; j += 4)
                *reinterpret_cast<float4*>(&b[j]) =
                    *reinterpret_cast<const float4*>(&Bs[kk][tx * 8 + j]);
#pragma unroll
            for (int i = 0; i < 8; i++)
#pragma unroll
                for (int j = 0; j < 8; j++)
                    acc[i][j] = fmaf(a[i], b[j], acc[i][j]);
        }
        __syncthreads();
    }

    // ---- epilogue ----
#pragma unroll
    for (int i = 0; i < 8; i++) {
        int m = m0 + ty * 8 + i;
        float dsc = dis[m];
#pragma unroll
        for (int j = 0; j < 8; j++) {
            float v = acc[i][j] * dsc;
            if (EPI >= 1) v += bias[n0 + tx * 8 + j];
            if (EPI == 1) v = fmaxf(v, 0.f);
            acc[i][j] = v;
        }
#pragma unroll
        for (int j = 0; j < 8; j += 4)
            *reinterpret_cast<float4*>(&C[(long)m * ldc + n0 + tx * 8 + j]) =
                *reinterpret_cast<const float4*>(&acc[i][j]);
    }
}

// ---------------------------------------------------------------------------
// 3) LayerNorm each row of h2 [B,N,D] over D, then partial-sum over a chunk of
//    128 rows:  partial[b,ch,d] = ln_g[d]*sum_rows(norm) + 128*ln_b[d]
//    (deterministic two-stage reduction, no atomics)
// grid (8, B), block 256 = 8 warps; each warp owns rows w, w+8, ...
// ---------------------------------------------------------------------------
__global__ void ln_pool_partial(const float* __restrict__ h2,
                                const float* __restrict__ lng,
                                const float* __restrict__ lnb,
                                float* __restrict__ partial)
{
    int b  = blockIdx.y;
    int ch = blockIdx.x;
    int w  = threadIdx.x >> 5;
    int l  = threadIdx.x & 31;
    const float* base = h2 + ((size_t)b * NN + ch * 128) * DD;

    float accv[16];
#pragma unroll
    for (int c = 0; c < 16; c++) accv[c] = 0.f;

    for (int r = w; r < 128; r += 8) {
        const float* row = base + (size_t)r * DD;
        float x[16];
        float s = 0.f;
#pragma unroll
        for (int c = 0; c < 16; c++) { x[c] = row[l + 32 * c]; s += x[c]; }
#pragma unroll
        for (int o = 16; o; o >>= 1) s += __shfl_xor_sync(0xffffffffu, s, o);
        float mu = s * (1.f / DD);
        float s2 = 0.f;
#pragma unroll
        for (int c = 0; c < 16; c++) { float d = x[c] - mu; s2 += d * d; }
#pragma unroll
        for (int o = 16; o; o >>= 1) s2 += __shfl_xor_sync(0xffffffffu, s2, o);
        float rstd = rsqrtf(s2 * (1.f / DD) + LN_EPS);
#pragma unroll
        for (int c = 0; c < 16; c++) accv[c] += (x[c] - mu) * rstd;
    }

    __shared__ float wacc[8][DD];
#pragma unroll
    for (int c = 0; c < 16; c++) wacc[w][l + 32 * c] = accv[c];
    __syncthreads();

    for (int d = threadIdx.x; d < DD; d += 256) {
        float s = 0.f;
#pragma unroll
        for (int w2 = 0; w2 < 8; w2++) s += wacc[w2][d];
        partial[((size_t)b * 8 + ch) * DD + d] = lng[d] * s + 128.f * lnb[d];
    }
}

// z_pooled[b,d] = (1/N) * sum_ch partial[b,ch,d]
__global__ void pool_finalize(const float* __restrict__ partial,
                              float* __restrict__ zp)
{
    int b = blockIdx.x;
    int d = threadIdx.x;      // 512 threads
    float s = 0.f;
#pragma unroll
    for (int c = 0; c < 8; c++) s += partial[((size_t)b * 8 + c) * DD + d];
    zp[b * DD + d] = s * (1.f / NN);
}

// ---------------------------------------------------------------------------
// 4) Classifier head: one block (128 threads) per batch element.
// ---------------------------------------------------------------------------
__device__ __forceinline__ float blk_sum128(float v, volatile float* red)
{
    int t = threadIdx.x;
    red[t] = v;
    __syncthreads();
#pragma unroll
    for (int o = 64; o > 0; o >>= 1) {
        if (t < o) red[t] += red[t + o];
        __syncthreads();
    }
    float s = red[0];
    __syncthreads();
    return s;
}

__global__ void classifier_kernel(
    const float* __restrict__ zp_all,
    const float* __restrict__ Wc1, const float* __restrict__ bc1,
    const float* __restrict__ g1,  const float* __restrict__ t1p,
    const float* __restrict__ Wc2, const float* __restrict__ bc2,
    const float* __restrict__ g2,  const float* __restrict__ t2p,
    const float* __restrict__ Wc3, const float* __restrict__ bc3,
    float* __restrict__ logits)
{
    int b = blockIdx.x;
    int t = threadIdx.x;     // 128 threads
    __shared__ float zp[DD];
    __shared__ float c1[128];
    __shared__ float c2[64];
    __shared__ float red[128];

    for (int d = t; d < DD; d += 128) zp[d] = zp_all[b * DD + d];
    __syncthreads();

    // layer 1: [512]->[128], LN(128), relu
    float v = 0.f;
#pragma unroll 4
    for (int k = 0; k < DD; k++) v = fmaf(zp[k], Wc1[k * 128 + t], v);
    v += bc1[t];
    float mu = blk_sum128(v, red) * (1.f / 128.f);
    float d1 = v - mu;
    float var = blk_sum128(d1 * d1, red) * (1.f / 128.f);
    v = d1 * rsqrtf(var + LN_EPS) * g1[t] + t1p[t];
    v = fmaxf(v, 0.f);
    c1[t] = v;
    __syncthreads();

    // layer 2: [128]->[64], LN(64), relu
    float v2 = 0.f;
    if (t < 64) {
#pragma unroll 4
        for (int k = 0; k < 128; k++) v2 = fmaf(c1[k], Wc2[k * 64 + t], v2);
        v2 += bc2[t];
    }
    float mu2 = blk_sum128((t < 64) ? v2 : 0.f, red) * (1.f / 64.f);
    float d2 = (t < 64) ? (v2 - mu2) : 0.f;
    float var2 = blk_sum128(d2 * d2, red) * (1.f / 64.f);
    if (t < 64) {
        v2 = d2 * rsqrtf(var2 + LN_EPS) * g2[t] + t2p[t];
        v2 = fmaxf(v2, 0.f);
        c2[t] = v2;
    }
    __syncthreads();

    // layer 3: [64]->[4]
    if (t < 4) {
        float s = bc3[t];
#pragma unroll
        for (int k = 0; k < 64; k++) s = fmaf(c2[k], Wc3[k * 4 + t], s);
        logits[b * 4 + t] = s;
    }
}

// ---------------------------------------------------------------------------
// Launch
// ---------------------------------------------------------------------------
extern "C" void kernel_launch(void* const* d_in, const int* in_sizes, int n_in,
                              void* d_out, int out_size)
{
    const float* A   = (const float*)d_in[0];   // sc_matrix [B,N,N]
    const float* W1  = (const float*)d_in[1];
    const float* b1  = (const float*)d_in[2];
    const float* W2  = (const float*)d_in[3];
    const float* b2  = (const float*)d_in[4];
    const float* lng = (const float*)d_in[5];
    const float* lnb = (const float*)d_in[6];
    const float* Wc1 = (const float*)d_in[7];
    const float* bc1 = (const float*)d_in[8];
    const float* g1  = (const float*)d_in[9];
    const float* t1p = (const float*)d_in[10];
    const float* Wc2 = (const float*)d_in[11];
    const float* bc2 = (const float*)d_in[12];
    const float* g2  = (const float*)d_in[13];
    const float* t2p = (const float*)d_in[14];
    const float* Wc3 = (const float*)d_in[15];
    const float* bc3 = (const float*)d_in[16];

    float* out    = (float*)d_out;
    float* logits = out;                 // [32,4]
    float* zp     = out + BATCH * 4;     // [32,512]

    void *p0, *p1, *pd, *pp;
    cudaGetSymbolAddress(&p0, g_buf0);
    cudaGetSymbolAddress(&p1, g_buf1);
    cudaGetSymbolAddress(&pd, g_dis);
    cudaGetSymbolAddress(&pp, g_partial);
    float* buf0    = (float*)p0;
    float* buf1    = (float*)p1;
    float* dis     = (float*)pd;
    float* partial = (float*)pp;

    const long MN = (long)NN * NN;   // per-batch A stride
    const long MD = (long)NN * DD;   // per-batch feature stride

    // 1) dis = rsqrt(colsum(A))
    deg_kernel<<<dim3(NN / 256, BATCH), 256>>>(A, dis);

    // 2) buf0 = dis ⊙ (x @ W1)   — flat GEMM M=32768,K=1024,N=512
    gemm_k<0, 0><<<dim3(DD / BN, (BATCH * NN) / BM, 1), 256>>>(
        A, W1, buf0, NN, NN, DD, DD, 0, 0, 0, dis, 0, nullptr);

    // 3) buf1 = relu(dis ⊙ (A^T @ buf0) + b1)  — batched
    gemm_k<1, 1><<<dim3(DD / BN, NN / BM, BATCH), 256>>>(
        A, buf0, buf1, NN, NN, DD, DD, MN, MD, MD, dis, NN, b1);

    // 4) buf0 = dis ⊙ (buf1 @ W2)  — flat, K=512
    gemm_k<0, 0><<<dim3(DD / BN, (BATCH * NN) / BM, 1), 256>>>(
        buf1, W2, buf0, DD, DD, DD, DD, 0, 0, 0, dis, 0, nullptr);

    // 5) buf1 = dis ⊙ (A^T @ buf0) + b2  (= h2) — batched
    gemm_k<1, 2><<<dim3(DD / BN, NN / BM, BATCH), 256>>>(
        A, buf0, buf1, NN, NN, DD, DD, MN, MD, MD, dis, NN, b2);

    // 6) LayerNorm + mean-pool (two deterministic stages)
    ln_pool_partial<<<dim3(8, BATCH), 256>>>(buf1, lng, lnb, partial);
    pool_finalize<<<BATCH, DD>>>(partial, zp);

    // 7) classifier head
    classifier_kernel<<<BATCH, 128>>>(zp, Wc1, bc1, g1, t1p,
                                      Wc2, bc2, g2, t2p, Wc3, bc3, logits);
}